// round 11
// baseline (speedup 1.0000x reference)
#include <cuda_runtime.h>
#include <cstdint>

// MultiIndexSelect: out[to_k[i]] = mat_k[from_k[i]], k=0..2, L=400000 rows, D=64 f32.
// Row = 256 B = 16 float4 slots. Evidence R4/R9/R10: DRAM pinned 54-66% across MLP
// configs; traffic near-compulsory (~490MB measured); LTS ~8.5TB/s co-limit.
// This round: cp.async gathers (register-free in-flight), UNROLL=6 (24KB smem ->
// ~87% occ), exact-divide grid (12500 blocks, no tail), per-slot commit groups
// with staged waits so scatter stores overlap the tail of the gather burst.

static constexpr int UNROLL  = 6;
static constexpr int THREADS = 256;

__global__ __launch_bounds__(THREADS) void multi_index_select_kernel(
    const float4* __restrict__ m0,
    const float4* __restrict__ m1,
    const float4* __restrict__ m2,
    const int* __restrict__ f0,
    const int* __restrict__ f1,
    const int* __restrict__ f2,
    const int* __restrict__ t0,
    const int* __restrict__ t1,
    const int* __restrict__ t2,
    float4* __restrict__ out,
    int L)
{
    __shared__ float4 buf[THREADS * UNROLL];            // 24 KB, private slot per (thread,u)

    const unsigned total = 3u * (unsigned)L * 16u;      // 19.2M slots
    const unsigned base  = blockIdx.x * (THREADS * UNROLL) + threadIdx.x;

    const unsigned smem_base =
        (unsigned)__cvta_generic_to_shared(buf) + threadIdx.x * 16u;

    unsigned dslot[UNROLL];
    bool     ok[UNROLL];

    // Phase 1: index loads + register-free gathers into smem.
    // One commit group per slot -> staged waits below.
    #pragma unroll
    for (int u = 0; u < UNROLL; u++) {
        unsigned tid = base + u * THREADS;
        ok[u] = (tid < total);
        if (ok[u]) {
            unsigned row  = tid >> 4;
            unsigned lane = tid & 15u;
            const float4* __restrict__ mat;
            int src, dst;
            if (row < (unsigned)L) {
                mat = m0; src = __ldg(&f0[row]);        dst = __ldg(&t0[row]);
            } else if (row < 2u * (unsigned)L) {
                unsigned r = row - (unsigned)L;
                mat = m1; src = __ldg(&f1[r]);          dst = __ldg(&t1[r]);
            } else {
                unsigned r = row - 2u * (unsigned)L;
                mat = m2; src = __ldg(&f2[r]);          dst = __ldg(&t2[r]);
            }
            dslot[u] = (unsigned)dst * 16u + lane;
            const float4* gsrc = &mat[(size_t)src * 16u + lane];
            unsigned saddr = smem_base + (unsigned)(u * THREADS) * 16u;
            asm volatile("cp.async.cg.shared.global [%0], [%1], 16;\n"
                         :: "r"(saddr), "l"(gsrc) : "memory");
        }
        asm volatile("cp.async.commit_group;\n" ::: "memory");
    }

    // Phase 2: staged drain — store slot u as soon as its group has landed,
    // while later gathers are still in flight (smooths read/write mix at DRAM).
    #pragma unroll
    for (int u = 0; u < UNROLL; u++) {
        switch (UNROLL - 1 - u) {   // groups still allowed outstanding
            case 5: asm volatile("cp.async.wait_group 5;\n" ::: "memory"); break;
            case 4: asm volatile("cp.async.wait_group 4;\n" ::: "memory"); break;
            case 3: asm volatile("cp.async.wait_group 3;\n" ::: "memory"); break;
            case 2: asm volatile("cp.async.wait_group 2;\n" ::: "memory"); break;
            case 1: asm volatile("cp.async.wait_group 1;\n" ::: "memory"); break;
            default: asm volatile("cp.async.wait_group 0;\n" ::: "memory"); break;
        }
        if (ok[u]) {
            float4 v = buf[u * THREADS + threadIdx.x];
            __stcs(&out[dslot[u]], v);
        }
    }
}

extern "C" void kernel_launch(void* const* d_in, const int* in_sizes, int n_in,
                              void* d_out, int out_size)
{
    const float4* m0 = (const float4*)d_in[0];
    const float4* m1 = (const float4*)d_in[1];
    const float4* m2 = (const float4*)d_in[2];
    const int* f0 = (const int*)d_in[3];
    const int* f1 = (const int*)d_in[4];
    const int* f2 = (const int*)d_in[5];
    const int* t0 = (const int*)d_in[6];
    const int* t1 = (const int*)d_in[7];
    const int* t2 = (const int*)d_in[8];

    int L = in_sizes[3];                                 // 400000
    unsigned total = 3u * (unsigned)L * 16u;
    unsigned per_block = THREADS * UNROLL;               // 1536
    unsigned blocks = (total + per_block - 1) / per_block;   // 12500 exact for L=400000

    multi_index_select_kernel<<<blocks, THREADS>>>(
        m0, m1, m2, f0, f1, f2, t0, t1, t2, (float4*)d_out, L);
}